// round 14
// baseline (speedup 1.0000x reference)
#include <cuda_runtime.h>
#include <cuda_fp16.h>
#include <math.h>

#define Bn 16
#define C  128
#define P  4096      // 64*64
#define TD 256
#define CD 256
#define E  8
#define NK 2

// ---------------- scratch (static device arrays) ---------------------------
__device__ __half g_t1[Bn*C*P];         // dwconv(proj) output (fp16)
__device__ __half g_xproj[Bn*C*P];      // x_proj (fp16)
__device__ __half g_t2[Bn*NK*C*P];      // expert dwconv outputs (fp16)
__device__ __half g_wproj_h[C*C];       // proj_pw weights, fp16 (pre-converted)
__device__ __half g_wexp_h[E*C*C];      // exp_pw weights, fp16 (pre-converted)
__device__ float  g_pooled[Bn*C];       // SUM over pixels (mean in router)
__device__ int    g_eidx[Bn*NK];
__device__ float  g_ew[Bn*NK];

__device__ __forceinline__ float silu_f(float v) {
    return v / (1.f + __expf(-v));
}

// D(16x8,f32) += A(16x16,f16) * B(16x8,f16)
__device__ __forceinline__ void mma_f16(float* c,
                                        unsigned a0, unsigned a1, unsigned a2, unsigned a3,
                                        unsigned b0, unsigned b1) {
    asm volatile("mma.sync.aligned.m16n8k16.row.col.f32.f16.f16.f32 "
                 "{%0,%1,%2,%3}, {%4,%5,%6,%7}, {%8,%9}, {%0,%1,%2,%3};"
                 : "+f"(c[0]), "+f"(c[1]), "+f"(c[2]), "+f"(c[3])
                 : "r"(a0), "r"(a1), "r"(a2), "r"(a3), "r"(b0), "r"(b1));
}

// warp-collective: load 4 x m8n8 b16 matrices (one m16k16 A fragment)
__device__ __forceinline__ void ldsm_x4(unsigned& r0, unsigned& r1,
                                        unsigned& r2, unsigned& r3,
                                        const unsigned* p) {
    unsigned addr = (unsigned)__cvta_generic_to_shared(p);
    asm volatile("ldmatrix.sync.aligned.m8n8.x4.shared.b16 {%0,%1,%2,%3}, [%4];"
                 : "=r"(r0), "=r"(r1), "=r"(r2), "=r"(r3) : "r"(addr));
}

// pack 4 floats -> 4 halfs (8 bytes)
__device__ __forceinline__ uint2 pack_h4(float a, float b, float c, float d) {
    union { uint2 u; __half2 h[2]; } pk;
    pk.h[0] = __floats2half2_rn(a, b);
    pk.h[1] = __floats2half2_rn(c, d);
    return pk.u;
}
__device__ __forceinline__ float4 unpack_h4(uint2 u) {
    union { uint2 uu; __half2 h[2]; } pk; pk.uu = u;
    float2 f0 = __half22float2(pk.h[0]);
    float2 f1 = __half22float2(pk.h[1]);
    return make_float4(f0.x, f0.y, f1.x, f1.y);
}
// zip even/odd k rows (4 px each) into 4 half2 (k,k+1) words
__device__ __forceinline__ uint4 zip_h4(uint2 e, uint2 o) {
    uint4 r;
    r.x = __byte_perm(e.x, o.x, 0x5410);
    r.y = __byte_perm(e.x, o.x, 0x7632);
    r.z = __byte_perm(e.y, o.y, 0x5410);
    r.w = __byte_perm(e.y, o.y, 0x7632);
    return r;
}

// ---------------- 1) proj dw 3x3 (2 rows/thread) + zero pooled + W cvt -----
__global__ void dw_proj_kernel(const float* __restrict__ x,
                               const float* __restrict__ w,
                               const float* __restrict__ bias,
                               const float* __restrict__ proj_pw,
                               const float* __restrict__ exp_pw) {
    int idx = blockIdx.x * blockDim.x + threadIdx.x;   // over Bn*C*512
    if (idx < Bn * C) g_pooled[idx] = 0.f;
    if (idx < C * C) g_wproj_h[idx] = __float2half_rn(proj_pw[idx]);
    if (idx < E * C * C) g_wexp_h[idx] = __float2half_rn(exp_pw[idx]);
    if (idx >= Bn*C*512) return;
    int q = idx & 511;
    int px0 = (q & 15) << 2;
    int py  = (q >> 4) << 1;          // 0,2,...,62
    int plane = idx >> 9;             // b*C + c
    int c = plane & 127;
    const float* xp = x + ((size_t)plane << 12);
    const float* wc = w + c * 9;
    float bb = bias[c];

    float4 m[4]; float rl[4], rr[4];
    #pragma unroll
    for (int r = 0; r < 4; r++) {
        int yy = py - 1 + r;
        if ((unsigned)yy < 64u) {
            const float* row = xp + (yy << 6);
            m[r] = *(const float4*)&row[px0];
            rl[r] = (px0 == 0)  ? 0.f : row[px0 - 1];
            rr[r] = (px0 == 60) ? 0.f : row[px0 + 4];
        } else {
            m[r] = make_float4(0.f, 0.f, 0.f, 0.f); rl[r] = 0.f; rr[r] = 0.f;
        }
    }
    float o0[4] = {bb, bb, bb, bb}, o1[4] = {bb, bb, bb, bb};
    #pragma unroll
    for (int j = 0; j < 3; j++) {
        float w0 = wc[j*3], w1 = wc[j*3+1], w2 = wc[j*3+2];
        float4 a = m[j];     float al = rl[j],     ar = rr[j];
        float4 bq = m[j+1];  float bl = rl[j+1],   br = rr[j+1];
        o0[0] += w0*al  + w1*a.x + w2*a.y;
        o0[1] += w0*a.x + w1*a.y + w2*a.z;
        o0[2] += w0*a.y + w1*a.z + w2*a.w;
        o0[3] += w0*a.z + w1*a.w + w2*ar;
        o1[0] += w0*bl   + w1*bq.x + w2*bq.y;
        o1[1] += w0*bq.x + w1*bq.y + w2*bq.z;
        o1[2] += w0*bq.y + w1*bq.z + w2*bq.w;
        o1[3] += w0*bq.z + w1*bq.w + w2*br;
    }
    size_t base = (size_t)plane << 12;
    *(uint2*)&g_t1[base + (py << 6) + px0]       = pack_h4(o0[0], o0[1], o0[2], o0[3]);
    *(uint2*)&g_t1[base + ((py+1) << 6) + px0]   = pack_h4(o1[0], o1[1], o1[2], o1[3]);
}

// ---------------- 2) proj pw GEMM (fp16 MMA, double-buffered, LDSM) --------
#define WSP 20
#define BSP 72
__global__ __launch_bounds__(256)
void pw_proj_kernel(const float* __restrict__ bias) {
    int b  = blockIdx.y;
    int p0 = blockIdx.x * 64;
    int tx = threadIdx.x;
    int wid = tx >> 5, lane = tx & 31;
    int wm = wid >> 1, wn = wid & 1;
    int g = lane >> 2, t4 = lane & 3;
    // ldmatrix lane mapping
    int arow_off = ((lane >> 3) & 1) * 8 + (lane & 7);
    int akoff    = (lane >> 4) * 4;      // +16B for k8-15 matrices
    __shared__ __align__(16) unsigned Wsm[2][128 * WSP];
    __shared__ __align__(16) unsigned Bsm[2][16 * BSP];
    float acc[2][4][4];
    #pragma unroll
    for (int i = 0; i < 2; i++)
        #pragma unroll
        for (int j = 0; j < 4; j++)
            #pragma unroll
            for (int l = 0; l < 4; l++) acc[i][j][l] = 0.f;

    const __half* tin = g_t1 + (((size_t)b * C) << 12) + p0;
    int wco[2], wk8[2];
    #pragma unroll
    for (int i = 0; i < 2; i++) { int s = i * 256 + tx; wco[i] = s >> 2; wk8[i] = s & 3; }
    int k2 = tx >> 4, bpx0 = (tx & 15) << 2;

    uint4 wraw[2]; uint2 be, bo;
    #pragma unroll
    for (int i = 0; i < 2; i++)
        wraw[i] = *(const uint4*)&g_wproj_h[wco[i] * C + wk8[i] * 8];
    be = *(const uint2*)&tin[(size_t)(2 * k2) * P + bpx0];
    bo = *(const uint2*)&tin[(size_t)(2 * k2 + 1) * P + bpx0];
    #pragma unroll
    for (int i = 0; i < 2; i++)
        *(uint4*)&Wsm[0][wco[i] * WSP + wk8[i] * 4] = wraw[i];
    *(uint4*)&Bsm[0][k2 * BSP + bpx0] = zip_h4(be, bo);
    __syncthreads();

    for (int ci = 0; ci < 4; ci++) {
        int cur = ci & 1;
        if (ci < 3) {                          // gmem loads for next chunk
            int c0 = (ci + 1) * 32;
            #pragma unroll
            for (int i = 0; i < 2; i++)
                wraw[i] = *(const uint4*)&g_wproj_h[wco[i] * C + c0 + wk8[i] * 8];
            be = *(const uint2*)&tin[(size_t)(c0 + 2 * k2) * P + bpx0];
            bo = *(const uint2*)&tin[(size_t)(c0 + 2 * k2 + 1) * P + bpx0];
        }
        const unsigned* Wc = Wsm[cur];
        const unsigned* Bc = Bsm[cur];
        #pragma unroll
        for (int kk = 0; kk < 2; kk++) {
            unsigned af[2][4];
            #pragma unroll
            for (int mt = 0; mt < 2; mt++) {
                int arow = wm * 32 + mt * 16 + arow_off;
                ldsm_x4(af[mt][0], af[mt][1], af[mt][2], af[mt][3],
                        &Wc[arow * WSP + kk * 8 + akoff]);
            }
            #pragma unroll
            for (int nt = 0; nt < 4; nt++) {
                int col = wn * 32 + nt * 8 + g;
                unsigned b0 = Bc[(kk * 8 + t4) * BSP + col];
                unsigned b1 = Bc[(kk * 8 + t4 + 4) * BSP + col];
                #pragma unroll
                for (int mt = 0; mt < 2; mt++)
                    mma_f16(acc[mt][nt], af[mt][0], af[mt][1], af[mt][2], af[mt][3], b0, b1);
            }
        }
        if (ci < 3) {
            int nxt = 1 - cur;
            #pragma unroll
            for (int i = 0; i < 2; i++)
                *(uint4*)&Wsm[nxt][wco[i] * WSP + wk8[i] * 4] = wraw[i];
            *(uint4*)&Bsm[nxt][k2 * BSP + bpx0] = zip_h4(be, bo);
            __syncthreads();
        }
    }
    // epilogue: bias, store xproj (fp16), pooled partials (fp32)
    #pragma unroll
    for (int mt = 0; mt < 2; mt++) {
        int r0 = wm * 32 + mt * 16 + g;
        float bb0 = bias[r0], bb8 = bias[r0 + 8];
        float s0 = 0.f, s8 = 0.f;
        #pragma unroll
        for (int nt = 0; nt < 4; nt++) {
            int col = p0 + wn * 32 + nt * 8 + 2 * t4;
            __half* o0 = g_xproj + ((((size_t)b * C) + r0) << 12) + col;
            __half* o8 = g_xproj + ((((size_t)b * C) + r0 + 8) << 12) + col;
            float v0 = acc[mt][nt][0] + bb0, v1 = acc[mt][nt][1] + bb0;
            float v2 = acc[mt][nt][2] + bb8, v3 = acc[mt][nt][3] + bb8;
            *(__half2*)o0 = __floats2half2_rn(v0, v1);
            *(__half2*)o8 = __floats2half2_rn(v2, v3);
            s0 += v0 + v1; s8 += v2 + v3;
        }
        s0 += __shfl_down_sync(0xffffffffu, s0, 2, 4);
        s0 += __shfl_down_sync(0xffffffffu, s0, 1, 4);
        s8 += __shfl_down_sync(0xffffffffu, s8, 2, 4);
        s8 += __shfl_down_sync(0xffffffffu, s8, 1, 4);
        if (t4 == 0) {
            atomicAdd(&g_pooled[b * C + r0], s0);
            atomicAdd(&g_pooled[b * C + r0 + 8], s8);
        }
    }
}

// ---------------- 3) router: per-b block, fused MLP+top2 -------------------
__global__ __launch_bounds__(1024)
void router_kernel(const float* __restrict__ t_emb,
                   const float* __restrict__ c_emb,
                   const float* __restrict__ W1, const float* __restrict__ b1,
                   const float* __restrict__ W2, const float* __restrict__ b2,
                   float* __restrict__ out_logits) {
    int b = blockIdx.x;
    __shared__ float feat[C + TD + CD];
    __shared__ float hpart[8][C];
    __shared__ float h[C];
    __shared__ float lgp[8][E];
    __shared__ float lg[E];
    int t = threadIdx.x;
    if (t < C + TD + CD) {
        float v;
        if (t < C)            v = g_pooled[b * C + t] * (1.f / 4096.f);
        else if (t < C + TD)  v = t_emb[b * TD + (t - C)];
        else                  v = c_emb[b * CD + (t - C - TD)];
        feat[t] = v;
    }
    __syncthreads();
    int co = t & 127, chunk = t >> 7;
    {
        float a0 = 0.f, a1 = 0.f, a2 = 0.f, a3 = 0.f;
        int f0 = chunk * 80;
        #pragma unroll
        for (int f = f0; f < f0 + 80; f += 4) {
            a0 += feat[f]     * W1[f * C + co];
            a1 += feat[f + 1] * W1[(f + 1) * C + co];
            a2 += feat[f + 2] * W1[(f + 2) * C + co];
            a3 += feat[f + 3] * W1[(f + 3) * C + co];
        }
        hpart[chunk][co] = (a0 + a1) + (a2 + a3);
    }
    __syncthreads();
    if (t < C) {
        float v = b1[t];
        #pragma unroll
        for (int i = 0; i < 8; i++) v += hpart[i][t];
        h[t] = silu_f(v);
    }
    __syncthreads();
    if (t < 64) {
        int e = t & 7, pp = t >> 3;
        float a = 0.f;
        int c0 = pp * 16;
        #pragma unroll
        for (int ci = c0; ci < c0 + 16; ci++) a += h[ci] * W2[ci * E + e];
        lgp[pp][e] = a;
    }
    __syncthreads();
    if (t < E) {
        float a = b2[t];
        #pragma unroll
        for (int i = 0; i < 8; i++) a += lgp[i][t];
        lg[t] = a;
        out_logits[b * E + t] = a;
    }
    __syncthreads();
    if (t == 0) {
        int i0 = 0; float v0 = lg[0];
        for (int e = 1; e < E; e++) if (lg[e] > v0) { v0 = lg[e]; i0 = e; }
        int i1 = -1; float v1 = -3.0e38f;
        for (int e = 0; e < E; e++) {
            if (e == i0) continue;
            if (lg[e] > v1) { v1 = lg[e]; i1 = e; }
        }
        float w0 = 1.f / (1.f + __expf(v1 - v0));
        g_eidx[b*2]   = i0;  g_eidx[b*2+1] = i1;
        g_ew[b*2]     = w0;  g_ew[b*2+1]   = 1.f - w0;
    }
}

// ---------------- 4) expert dw 3x3 — 2 experts, 2 rows / thread ------------
__global__ void dw_exp_kernel(const float* __restrict__ w,
                              const float* __restrict__ bias) {
    int idx = blockIdx.x * blockDim.x + threadIdx.x;   // over Bn*C*512
    if (idx >= Bn*C*512) return;
    int q = idx & 511;
    int px0 = (q & 15) << 2;
    int py  = (q >> 4) << 1;
    int plane = idx >> 9;             // b*C + c
    int c = plane & 127;
    int b = plane >> 7;
    int e0 = g_eidx[b*2], e1 = g_eidx[b*2+1];
    const __half* xp = g_xproj + ((size_t)plane << 12);
    const float* wcA = w + ((size_t)e0 * C + c) * 9;
    const float* wcB = w + ((size_t)e1 * C + c) * 9;
    float bA = bias[e0 * C + c], bB = bias[e1 * C + c];

    float4 m[4]; float rl[4], rr[4];
    #pragma unroll
    for (int r = 0; r < 4; r++) {
        int yy = py - 1 + r;
        if ((unsigned)yy < 64u) {
            const __half* row = xp + (yy << 6);
            m[r] = unpack_h4(*(const uint2*)&row[px0]);
            rl[r] = (px0 == 0)  ? 0.f : __half2float(row[px0 - 1]);
            rr[r] = (px0 == 60) ? 0.f : __half2float(row[px0 + 4]);
        } else {
            m[r] = make_float4(0.f, 0.f, 0.f, 0.f); rl[r] = 0.f; rr[r] = 0.f;
        }
    }
    float A0[4] = {bA, bA, bA, bA}, A1[4] = {bA, bA, bA, bA};
    float B0[4] = {bB, bB, bB, bB}, B1[4] = {bB, bB, bB, bB};
    #pragma unroll
    for (int j = 0; j < 3; j++) {
        float wa0 = wcA[j*3], wa1 = wcA[j*3+1], wa2 = wcA[j*3+2];
        float wb0 = wcB[j*3], wb1 = wcB[j*3+1], wb2 = wcB[j*3+2];
        float4 a = m[j];    float al = rl[j],   ar = rr[j];
        float4 bq = m[j+1]; float bl = rl[j+1], br = rr[j+1];
        A0[0] += wa0*al  + wa1*a.x + wa2*a.y;
        A0[1] += wa0*a.x + wa1*a.y + wa2*a.z;
        A0[2] += wa0*a.y + wa1*a.z + wa2*a.w;
        A0[3] += wa0*a.z + wa1*a.w + wa2*ar;
        A1[0] += wa0*bl   + wa1*bq.x + wa2*bq.y;
        A1[1] += wa0*bq.x + wa1*bq.y + wa2*bq.z;
        A1[2] += wa0*bq.y + wa1*bq.z + wa2*bq.w;
        A1[3] += wa0*bq.z + wa1*bq.w + wa2*br;
        B0[0] += wb0*al  + wb1*a.x + wb2*a.y;
        B0[1] += wb0*a.x + wb1*a.y + wb2*a.z;
        B0[2] += wb0*a.y + wb1*a.z + wb2*a.w;
        B0[3] += wb0*a.z + wb1*a.w + wb2*ar;
        B1[0] += wb0*bl   + wb1*bq.x + wb2*bq.y;
        B1[1] += wb0*bq.x + wb1*bq.y + wb2*bq.z;
        B1[2] += wb0*bq.y + wb1*bq.z + wb2*bq.w;
        B1[3] += wb0*bq.z + wb1*bq.w + wb2*br;
    }
    size_t baseA = (size_t)((b*2 + 0) * C + c) << 12;
    size_t baseB = (size_t)((b*2 + 1) * C + c) << 12;
    size_t off0 = (py << 6) + px0, off1 = ((py+1) << 6) + px0;
    *(uint2*)&g_t2[baseA + off0] = pack_h4(A0[0], A0[1], A0[2], A0[3]);
    *(uint2*)&g_t2[baseA + off1] = pack_h4(A1[0], A1[1], A1[2], A1[3]);
    *(uint2*)&g_t2[baseB + off0] = pack_h4(B0[0], B0[1], B0[2], B0[3]);
    *(uint2*)&g_t2[baseB + off1] = pack_h4(B1[0], B1[1], B1[2], B1[3]);
}

// ---------------- 5) expert pw GEMM x2 (fp16 MMA, double-buffered, LDSM) ---
#define WSE 12
__global__ __launch_bounds__(256, 2)
void pw_exp_kernel(const float* __restrict__ bias, float* __restrict__ out) {
    int b  = blockIdx.y;
    int p0 = blockIdx.x * 64;
    int tx = threadIdx.x;
    int wid = tx >> 5, lane = tx & 31;
    int wm = wid >> 1, wn = wid & 1;
    int g = lane >> 2, t4 = lane & 3;
    int arow_off = ((lane >> 3) & 1) * 8 + (lane & 7);
    int akoff    = (lane >> 4) * 4;
    int e0 = g_eidx[b*2], e1 = g_eidx[b*2+1];
    float rw0 = g_ew[b*2], rw1 = g_ew[b*2+1];
    __shared__ __align__(16) unsigned Wsm0[2][128 * WSE], Wsm1[2][128 * WSE];
    __shared__ __align__(16) unsigned Bsm0[2][8 * BSP],   Bsm1[2][8 * BSP];
    float a0c[2][4][4], a1c[2][4][4];
    #pragma unroll
    for (int i = 0; i < 2; i++)
        #pragma unroll
        for (int j = 0; j < 4; j++)
            #pragma unroll
            for (int l = 0; l < 4; l++) { a0c[i][j][l] = 0.f; a1c[i][j][l] = 0.f; }

    const __half* t0 = g_t2 + (((size_t)(b*2 + 0) * C) << 12) + p0;
    const __half* t1 = g_t2 + (((size_t)(b*2 + 1) * C) << 12) + p0;
    const __half* W0 = g_wexp_h + (size_t)e0 * C * C;
    const __half* W1 = g_wexp_h + (size_t)e1 * C * C;

    int wco = tx >> 1, wk8 = tx & 1;
    int ex = tx >> 7, s7 = tx & 127;
    int k2 = s7 >> 4, bpx0 = (s7 & 15) << 2;
    const __half* tsel = ex ? t1 : t0;

    uint4 wraw0, wraw1; uint2 be, bo;
    wraw0 = *(const uint4*)&W0[wco * C + wk8 * 8];
    wraw1 = *(const uint4*)&W1[wco * C + wk8 * 8];
    be = *(const uint2*)&tsel[(size_t)(2 * k2) * P + bpx0];
    bo = *(const uint2*)&tsel[(size_t)(2 * k2 + 1) * P + bpx0];
    *(uint4*)&Wsm0[0][wco * WSE + wk8 * 4] = wraw0;
    *(uint4*)&Wsm1[0][wco * WSE + wk8 * 4] = wraw1;
    {
        unsigned* Bsel = ex ? Bsm1[0] : Bsm0[0];
        *(uint4*)&Bsel[k2 * BSP + bpx0] = zip_h4(be, bo);
    }
    __syncthreads();

    for (int ci = 0; ci < 8; ci++) {
        int cur = ci & 1;
        if (ci < 7) {
            int c0 = (ci + 1) * 16;
            wraw0 = *(const uint4*)&W0[wco * C + c0 + wk8 * 8];
            wraw1 = *(const uint4*)&W1[wco * C + c0 + wk8 * 8];
            be = *(const uint2*)&tsel[(size_t)(c0 + 2 * k2) * P + bpx0];
            bo = *(const uint2*)&tsel[(size_t)(c0 + 2 * k2 + 1) * P + bpx0];
        }
        const unsigned* Wc0 = Wsm0[cur];
        const unsigned* Wc1 = Wsm1[cur];
        const unsigned* Bc0 = Bsm0[cur];
        const unsigned* Bc1 = Bsm1[cur];
        unsigned af0[2][4], af1[2][4];
        #pragma unroll
        for (int mt = 0; mt < 2; mt++) {
            int arow = wm * 32 + mt * 16 + arow_off;
            ldsm_x4(af0[mt][0], af0[mt][1], af0[mt][2], af0[mt][3],
                    &Wc0[arow * WSE + akoff]);
            ldsm_x4(af1[mt][0], af1[mt][1], af1[mt][2], af1[mt][3],
                    &Wc1[arow * WSE + akoff]);
        }
        #pragma unroll
        for (int nt = 0; nt < 4; nt++) {
            int col = wn * 32 + nt * 8 + g;
            unsigned b00 = Bc0[t4 * BSP + col];
            unsigned b01 = Bc0[(t4 + 4) * BSP + col];
            unsigned b10 = Bc1[t4 * BSP + col];
            unsigned b11 = Bc1[(t4 + 4) * BSP + col];
            #pragma unroll
            for (int mt = 0; mt < 2; mt++) {
                mma_f16(a0c[mt][nt], af0[mt][0], af0[mt][1], af0[mt][2], af0[mt][3], b00, b01);
                mma_f16(a1c[mt][nt], af1[mt][0], af1[mt][1], af1[mt][2], af1[mt][3], b10, b11);
            }
        }
        if (ci < 7) {
            int nxt = 1 - cur;
            *(uint4*)&Wsm0[nxt][wco * WSE + wk8 * 4] = wraw0;
            *(uint4*)&Wsm1[nxt][wco * WSE + wk8 * 4] = wraw1;
            unsigned* Bsel = ex ? Bsm1[nxt] : Bsm0[nxt];
            *(uint4*)&Bsel[k2 * BSP + bpx0] = zip_h4(be, bo);
            __syncthreads();
        }
    }
    #pragma unroll
    for (int mt = 0; mt < 2; mt++) {
        int r0 = wm * 32 + mt * 16 + g;
        float b00 = bias[e0 * C + r0], b08 = bias[e0 * C + r0 + 8];
        float b10 = bias[e1 * C + r0], b18 = bias[e1 * C + r0 + 8];
        #pragma unroll
        for (int nt = 0; nt < 4; nt++) {
            int col = p0 + wn * 32 + nt * 8 + 2 * t4;
            float* o0 = out + ((((size_t)b * C) + r0) << 12) + col;
            float* o8 = out + ((((size_t)b * C) + r0 + 8) << 12) + col;
            float v0 = rw0 * silu_f(a0c[mt][nt][0] + b00) + rw1 * silu_f(a1c[mt][nt][0] + b10);
            float v1 = rw0 * silu_f(a0c[mt][nt][1] + b00) + rw1 * silu_f(a1c[mt][nt][1] + b10);
            float v2 = rw0 * silu_f(a0c[mt][nt][2] + b08) + rw1 * silu_f(a1c[mt][nt][2] + b18);
            float v3 = rw0 * silu_f(a0c[mt][nt][3] + b08) + rw1 * silu_f(a1c[mt][nt][3] + b18);
            *(float2*)o0 = make_float2(v0, v1);
            *(float2*)o8 = make_float2(v2, v3);
        }
    }
}

// ---------------- launch ----------------------------------------------------
extern "C" void kernel_launch(void* const* d_in, const int* in_sizes, int n_in,
                              void* d_out, int out_size) {
    const float* x         = (const float*)d_in[0];
    const float* t_emb     = (const float*)d_in[1];
    const float* c_emb     = (const float*)d_in[2];
    const float* proj_dw   = (const float*)d_in[3];
    const float* proj_dw_b = (const float*)d_in[4];
    const float* proj_pw   = (const float*)d_in[5];
    const float* proj_pw_b = (const float*)d_in[6];
    const float* r_w1      = (const float*)d_in[7];
    const float* r_b1      = (const float*)d_in[8];
    const float* r_w2      = (const float*)d_in[9];
    const float* r_b2      = (const float*)d_in[10];
    const float* exp_dw    = (const float*)d_in[11];
    const float* exp_dw_b  = (const float*)d_in[12];
    const float* exp_pw    = (const float*)d_in[13];
    const float* exp_pw_b  = (const float*)d_in[14];

    float* out        = (float*)d_out;
    float* out_logits = out + (size_t)Bn * C * P;

    dw_proj_kernel<<<(Bn*C*512 + 255) / 256, 256>>>(x, proj_dw, proj_dw_b, proj_pw, exp_pw);
    pw_proj_kernel<<<dim3(P / 64, Bn), 256>>>(proj_pw_b);
    router_kernel<<<Bn, 1024>>>(t_emb, c_emb, r_w1, r_b1, r_w2, r_b2, out_logits);
    dw_exp_kernel<<<(Bn*C*512 + 255) / 256, 256>>>(exp_dw, exp_dw_b);
    pw_exp_kernel<<<dim3(P / 64, Bn), 256>>>(exp_pw_b, out);
}

// round 15
// speedup vs baseline: 1.0507x; 1.0507x over previous
#include <cuda_runtime.h>
#include <cuda_fp16.h>
#include <math.h>

#define Bn 16
#define C  128
#define P  4096      // 64*64
#define TD 256
#define CD 256
#define E  8
#define NK 2

// ---------------- scratch (static device arrays) ---------------------------
__device__ __half g_t1[Bn*C*P];         // dwconv(proj) output (fp16)
__device__ __half g_xproj[Bn*C*P];      // x_proj (fp16)
__device__ __half g_t2[Bn*NK*C*P];      // expert dwconv outputs (fp16)
__device__ __half g_wproj_h[C*C];       // proj_pw weights, fp16 (pre-converted)
__device__ __half g_wexp_h[E*C*C];      // exp_pw weights, fp16 (pre-converted)
__device__ float  g_pooled[Bn*C];       // SUM over pixels (mean in router)
__device__ int    g_eidx[Bn*NK];
__device__ float  g_ew[Bn*NK];

__device__ __forceinline__ float silu_f(float v) {
    return v / (1.f + __expf(-v));
}

// D(16x8,f32) += A(16x16,f16) * B(16x8,f16)
__device__ __forceinline__ void mma_f16(float* c,
                                        unsigned a0, unsigned a1, unsigned a2, unsigned a3,
                                        unsigned b0, unsigned b1) {
    asm volatile("mma.sync.aligned.m16n8k16.row.col.f32.f16.f16.f32 "
                 "{%0,%1,%2,%3}, {%4,%5,%6,%7}, {%8,%9}, {%0,%1,%2,%3};"
                 : "+f"(c[0]), "+f"(c[1]), "+f"(c[2]), "+f"(c[3])
                 : "r"(a0), "r"(a1), "r"(a2), "r"(a3), "r"(b0), "r"(b1));
}

// pack 4 floats -> 4 halfs (8 bytes)
__device__ __forceinline__ uint2 pack_h4(float a, float b, float c, float d) {
    union { uint2 u; __half2 h[2]; } pk;
    pk.h[0] = __floats2half2_rn(a, b);
    pk.h[1] = __floats2half2_rn(c, d);
    return pk.u;
}
__device__ __forceinline__ float4 unpack_h4(uint2 u) {
    union { uint2 uu; __half2 h[2]; } pk; pk.uu = u;
    float2 f0 = __half22float2(pk.h[0]);
    float2 f1 = __half22float2(pk.h[1]);
    return make_float4(f0.x, f0.y, f1.x, f1.y);
}
// zip even/odd k rows (4 px each) into 4 half2 (k,k+1) words
__device__ __forceinline__ uint4 zip_h4(uint2 e, uint2 o) {
    uint4 r;
    r.x = __byte_perm(e.x, o.x, 0x5410);
    r.y = __byte_perm(e.x, o.x, 0x7632);
    r.z = __byte_perm(e.y, o.y, 0x5410);
    r.w = __byte_perm(e.y, o.y, 0x7632);
    return r;
}

// ---------------- 1) proj dw 3x3 (4px x 4 rows/thread) + zero + W cvt ------
__global__ void dw_proj_kernel(const float* __restrict__ x,
                               const float* __restrict__ w,
                               const float* __restrict__ bias,
                               const float* __restrict__ proj_pw,
                               const float* __restrict__ exp_pw) {
    int idx = blockIdx.x * blockDim.x + threadIdx.x;   // over Bn*C*256
    if (idx < Bn * C) g_pooled[idx] = 0.f;
    if (idx < C * C) g_wproj_h[idx] = __float2half_rn(proj_pw[idx]);
    if (idx < E * C * C) g_wexp_h[idx] = __float2half_rn(exp_pw[idx]);
    if (idx >= Bn*C*256) return;
    int q = idx & 255;
    int px0 = (q & 15) << 2;
    int py  = (q >> 4) << 2;          // 0,4,...,60
    int plane = idx >> 8;             // b*C + c
    int c = plane & 127;
    const float* xp = x + ((size_t)plane << 12);
    const float* wc = w + c * 9;
    float bb = bias[c];

    float4 m[6]; float rl[6], rr[6];
    #pragma unroll
    for (int r = 0; r < 6; r++) {
        int yy = py - 1 + r;
        if ((unsigned)yy < 64u) {
            const float* row = xp + (yy << 6);
            m[r] = *(const float4*)&row[px0];
            rl[r] = (px0 == 0)  ? 0.f : row[px0 - 1];
            rr[r] = (px0 == 60) ? 0.f : row[px0 + 4];
        } else {
            m[r] = make_float4(0.f, 0.f, 0.f, 0.f); rl[r] = 0.f; rr[r] = 0.f;
        }
    }
    float o[4][4];
    #pragma unroll
    for (int r = 0; r < 4; r++)
        #pragma unroll
        for (int i = 0; i < 4; i++) o[r][i] = bb;
    #pragma unroll
    for (int j = 0; j < 3; j++) {
        float w0 = wc[j*3], w1 = wc[j*3+1], w2 = wc[j*3+2];
        #pragma unroll
        for (int r = 0; r < 4; r++) {
            float4 a = m[r + j]; float al = rl[r + j], ar = rr[r + j];
            o[r][0] += w0*al  + w1*a.x + w2*a.y;
            o[r][1] += w0*a.x + w1*a.y + w2*a.z;
            o[r][2] += w0*a.y + w1*a.z + w2*a.w;
            o[r][3] += w0*a.z + w1*a.w + w2*ar;
        }
    }
    size_t base = ((size_t)plane << 12) + px0;
    #pragma unroll
    for (int r = 0; r < 4; r++)
        *(uint2*)&g_t1[base + ((py + r) << 6)] = pack_h4(o[r][0], o[r][1], o[r][2], o[r][3]);
}

// ---------------- 2) proj pw GEMM (fp16 MMA, double-buffered) + pool -------
#define WSP 20
#define BSP 72
__global__ __launch_bounds__(256)
void pw_proj_kernel(const float* __restrict__ bias) {
    int b  = blockIdx.y;
    int p0 = blockIdx.x * 64;
    int tx = threadIdx.x;
    int wid = tx >> 5, lane = tx & 31;
    int wm = wid >> 1, wn = wid & 1;
    int g = lane >> 2, t4 = lane & 3;
    __shared__ __align__(16) unsigned Wsm[2][128 * WSP];
    __shared__ __align__(16) unsigned Bsm[2][16 * BSP];
    float acc[2][4][4];
    #pragma unroll
    for (int i = 0; i < 2; i++)
        #pragma unroll
        for (int j = 0; j < 4; j++)
            #pragma unroll
            for (int l = 0; l < 4; l++) acc[i][j][l] = 0.f;

    const __half* tin = g_t1 + (((size_t)b * C) << 12) + p0;
    int wco[2], wk8[2];
    #pragma unroll
    for (int i = 0; i < 2; i++) { int s = i * 256 + tx; wco[i] = s >> 2; wk8[i] = s & 3; }
    int k2 = tx >> 4, bpx0 = (tx & 15) << 2;

    uint4 wraw[2]; uint2 be, bo;
    #pragma unroll
    for (int i = 0; i < 2; i++)
        wraw[i] = *(const uint4*)&g_wproj_h[wco[i] * C + wk8[i] * 8];
    be = *(const uint2*)&tin[(size_t)(2 * k2) * P + bpx0];
    bo = *(const uint2*)&tin[(size_t)(2 * k2 + 1) * P + bpx0];
    #pragma unroll
    for (int i = 0; i < 2; i++)
        *(uint4*)&Wsm[0][wco[i] * WSP + wk8[i] * 4] = wraw[i];
    *(uint4*)&Bsm[0][k2 * BSP + bpx0] = zip_h4(be, bo);
    __syncthreads();

    for (int ci = 0; ci < 4; ci++) {
        int cur = ci & 1;
        if (ci < 3) {                          // gmem loads for next chunk
            int c0 = (ci + 1) * 32;
            #pragma unroll
            for (int i = 0; i < 2; i++)
                wraw[i] = *(const uint4*)&g_wproj_h[wco[i] * C + c0 + wk8[i] * 8];
            be = *(const uint2*)&tin[(size_t)(c0 + 2 * k2) * P + bpx0];
            bo = *(const uint2*)&tin[(size_t)(c0 + 2 * k2 + 1) * P + bpx0];
        }
        const unsigned* Wc = Wsm[cur];
        const unsigned* Bc = Bsm[cur];
        #pragma unroll
        for (int kk = 0; kk < 2; kk++) {
            unsigned af[2][4];
            #pragma unroll
            for (int mt = 0; mt < 2; mt++) {
                int r0 = wm * 32 + mt * 16 + g;
                af[mt][0] = Wc[r0 * WSP + kk * 8 + t4];
                af[mt][1] = Wc[(r0 + 8) * WSP + kk * 8 + t4];
                af[mt][2] = Wc[r0 * WSP + kk * 8 + t4 + 4];
                af[mt][3] = Wc[(r0 + 8) * WSP + kk * 8 + t4 + 4];
            }
            #pragma unroll
            for (int nt = 0; nt < 4; nt++) {
                int col = wn * 32 + nt * 8 + g;
                unsigned b0 = Bc[(kk * 8 + t4) * BSP + col];
                unsigned b1 = Bc[(kk * 8 + t4 + 4) * BSP + col];
                #pragma unroll
                for (int mt = 0; mt < 2; mt++)
                    mma_f16(acc[mt][nt], af[mt][0], af[mt][1], af[mt][2], af[mt][3], b0, b1);
            }
        }
        if (ci < 3) {
            int nxt = 1 - cur;
            #pragma unroll
            for (int i = 0; i < 2; i++)
                *(uint4*)&Wsm[nxt][wco[i] * WSP + wk8[i] * 4] = wraw[i];
            *(uint4*)&Bsm[nxt][k2 * BSP + bpx0] = zip_h4(be, bo);
            __syncthreads();
        }
    }
    // epilogue: bias, store xproj (fp16), pooled partials (fp32)
    #pragma unroll
    for (int mt = 0; mt < 2; mt++) {
        int r0 = wm * 32 + mt * 16 + g;
        float bb0 = bias[r0], bb8 = bias[r0 + 8];
        float s0 = 0.f, s8 = 0.f;
        #pragma unroll
        for (int nt = 0; nt < 4; nt++) {
            int col = p0 + wn * 32 + nt * 8 + 2 * t4;
            __half* o0 = g_xproj + ((((size_t)b * C) + r0) << 12) + col;
            __half* o8 = g_xproj + ((((size_t)b * C) + r0 + 8) << 12) + col;
            float v0 = acc[mt][nt][0] + bb0, v1 = acc[mt][nt][1] + bb0;
            float v2 = acc[mt][nt][2] + bb8, v3 = acc[mt][nt][3] + bb8;
            *(__half2*)o0 = __floats2half2_rn(v0, v1);
            *(__half2*)o8 = __floats2half2_rn(v2, v3);
            s0 += v0 + v1; s8 += v2 + v3;
        }
        s0 += __shfl_down_sync(0xffffffffu, s0, 2, 4);
        s0 += __shfl_down_sync(0xffffffffu, s0, 1, 4);
        s8 += __shfl_down_sync(0xffffffffu, s8, 2, 4);
        s8 += __shfl_down_sync(0xffffffffu, s8, 1, 4);
        if (t4 == 0) {
            atomicAdd(&g_pooled[b * C + r0], s0);
            atomicAdd(&g_pooled[b * C + r0 + 8], s8);
        }
    }
}

// ---------------- 3) router: per-b block, fused MLP+top2 -------------------
__global__ __launch_bounds__(1024)
void router_kernel(const float* __restrict__ t_emb,
                   const float* __restrict__ c_emb,
                   const float* __restrict__ W1, const float* __restrict__ b1,
                   const float* __restrict__ W2, const float* __restrict__ b2,
                   float* __restrict__ out_logits) {
    int b = blockIdx.x;
    __shared__ float feat[C + TD + CD];
    __shared__ float hpart[8][C];
    __shared__ float h[C];
    __shared__ float lgp[8][E];
    __shared__ float lg[E];
    int t = threadIdx.x;
    if (t < C + TD + CD) {
        float v;
        if (t < C)            v = g_pooled[b * C + t] * (1.f / 4096.f);
        else if (t < C + TD)  v = t_emb[b * TD + (t - C)];
        else                  v = c_emb[b * CD + (t - C - TD)];
        feat[t] = v;
    }
    __syncthreads();
    int co = t & 127, chunk = t >> 7;
    {
        float a0 = 0.f, a1 = 0.f, a2 = 0.f, a3 = 0.f;
        int f0 = chunk * 80;
        #pragma unroll
        for (int f = f0; f < f0 + 80; f += 4) {
            a0 += feat[f]     * W1[f * C + co];
            a1 += feat[f + 1] * W1[(f + 1) * C + co];
            a2 += feat[f + 2] * W1[(f + 2) * C + co];
            a3 += feat[f + 3] * W1[(f + 3) * C + co];
        }
        hpart[chunk][co] = (a0 + a1) + (a2 + a3);
    }
    __syncthreads();
    if (t < C) {
        float v = b1[t];
        #pragma unroll
        for (int i = 0; i < 8; i++) v += hpart[i][t];
        h[t] = silu_f(v);
    }
    __syncthreads();
    if (t < 64) {
        int e = t & 7, pp = t >> 3;
        float a = 0.f;
        int c0 = pp * 16;
        #pragma unroll
        for (int ci = c0; ci < c0 + 16; ci++) a += h[ci] * W2[ci * E + e];
        lgp[pp][e] = a;
    }
    __syncthreads();
    if (t < E) {
        float a = b2[t];
        #pragma unroll
        for (int i = 0; i < 8; i++) a += lgp[i][t];
        lg[t] = a;
        out_logits[b * E + t] = a;
    }
    __syncthreads();
    if (t == 0) {
        int i0 = 0; float v0 = lg[0];
        for (int e = 1; e < E; e++) if (lg[e] > v0) { v0 = lg[e]; i0 = e; }
        int i1 = -1; float v1 = -3.0e38f;
        for (int e = 0; e < E; e++) {
            if (e == i0) continue;
            if (lg[e] > v1) { v1 = lg[e]; i1 = e; }
        }
        float w0 = 1.f / (1.f + __expf(v1 - v0));
        g_eidx[b*2]   = i0;  g_eidx[b*2+1] = i1;
        g_ew[b*2]     = w0;  g_ew[b*2+1]   = 1.f - w0;
    }
}

// ---------------- 4) expert dw 3x3 — 2 experts, 2 rows / thread ------------
__global__ void dw_exp_kernel(const float* __restrict__ w,
                              const float* __restrict__ bias) {
    int idx = blockIdx.x * blockDim.x + threadIdx.x;   // over Bn*C*512
    if (idx >= Bn*C*512) return;
    int q = idx & 511;
    int px0 = (q & 15) << 2;
    int py  = (q >> 4) << 1;
    int plane = idx >> 9;             // b*C + c
    int c = plane & 127;
    int b = plane >> 7;
    int e0 = g_eidx[b*2], e1 = g_eidx[b*2+1];
    const __half* xp = g_xproj + ((size_t)plane << 12);
    const float* wcA = w + ((size_t)e0 * C + c) * 9;
    const float* wcB = w + ((size_t)e1 * C + c) * 9;
    float bA = bias[e0 * C + c], bB = bias[e1 * C + c];

    float4 m[4]; float rl[4], rr[4];
    #pragma unroll
    for (int r = 0; r < 4; r++) {
        int yy = py - 1 + r;
        if ((unsigned)yy < 64u) {
            const __half* row = xp + (yy << 6);
            m[r] = unpack_h4(*(const uint2*)&row[px0]);
            rl[r] = (px0 == 0)  ? 0.f : __half2float(row[px0 - 1]);
            rr[r] = (px0 == 60) ? 0.f : __half2float(row[px0 + 4]);
        } else {
            m[r] = make_float4(0.f, 0.f, 0.f, 0.f); rl[r] = 0.f; rr[r] = 0.f;
        }
    }
    float A0[4] = {bA, bA, bA, bA}, A1[4] = {bA, bA, bA, bA};
    float B0[4] = {bB, bB, bB, bB}, B1[4] = {bB, bB, bB, bB};
    #pragma unroll
    for (int j = 0; j < 3; j++) {
        float wa0 = wcA[j*3], wa1 = wcA[j*3+1], wa2 = wcA[j*3+2];
        float wb0 = wcB[j*3], wb1 = wcB[j*3+1], wb2 = wcB[j*3+2];
        float4 a = m[j];    float al = rl[j],   ar = rr[j];
        float4 bq = m[j+1]; float bl = rl[j+1], br = rr[j+1];
        A0[0] += wa0*al  + wa1*a.x + wa2*a.y;
        A0[1] += wa0*a.x + wa1*a.y + wa2*a.z;
        A0[2] += wa0*a.y + wa1*a.z + wa2*a.w;
        A0[3] += wa0*a.z + wa1*a.w + wa2*ar;
        A1[0] += wa0*bl   + wa1*bq.x + wa2*bq.y;
        A1[1] += wa0*bq.x + wa1*bq.y + wa2*bq.z;
        A1[2] += wa0*bq.y + wa1*bq.z + wa2*bq.w;
        A1[3] += wa0*bq.z + wa1*bq.w + wa2*br;
        B0[0] += wb0*al  + wb1*a.x + wb2*a.y;
        B0[1] += wb0*a.x + wb1*a.y + wb2*a.z;
        B0[2] += wb0*a.y + wb1*a.z + wb2*a.w;
        B0[3] += wb0*a.z + wb1*a.w + wb2*ar;
        B1[0] += wb0*bl   + wb1*bq.x + wb2*bq.y;
        B1[1] += wb0*bq.x + wb1*bq.y + wb2*bq.z;
        B1[2] += wb0*bq.y + wb1*bq.z + wb2*bq.w;
        B1[3] += wb0*bq.z + wb1*bq.w + wb2*br;
    }
    size_t baseA = (size_t)((b*2 + 0) * C + c) << 12;
    size_t baseB = (size_t)((b*2 + 1) * C + c) << 12;
    size_t off0 = (py << 6) + px0, off1 = ((py+1) << 6) + px0;
    *(uint2*)&g_t2[baseA + off0] = pack_h4(A0[0], A0[1], A0[2], A0[3]);
    *(uint2*)&g_t2[baseA + off1] = pack_h4(A1[0], A1[1], A1[2], A1[3]);
    *(uint2*)&g_t2[baseB + off0] = pack_h4(B0[0], B0[1], B0[2], B0[3]);
    *(uint2*)&g_t2[baseB + off1] = pack_h4(B1[0], B1[1], B1[2], B1[3]);
}

// ---------------- 5) expert pw GEMM x2 (fp16 MMA, double-buffered) ---------
#define WSE 12
__global__ __launch_bounds__(256, 2)
void pw_exp_kernel(const float* __restrict__ bias, float* __restrict__ out) {
    int b  = blockIdx.y;
    int p0 = blockIdx.x * 64;
    int tx = threadIdx.x;
    int wid = tx >> 5, lane = tx & 31;
    int wm = wid >> 1, wn = wid & 1;
    int g = lane >> 2, t4 = lane & 3;
    int e0 = g_eidx[b*2], e1 = g_eidx[b*2+1];
    float rw0 = g_ew[b*2], rw1 = g_ew[b*2+1];
    __shared__ __align__(16) unsigned Wsm0[2][128 * WSE], Wsm1[2][128 * WSE];
    __shared__ __align__(16) unsigned Bsm0[2][8 * BSP],   Bsm1[2][8 * BSP];
    float a0c[2][4][4], a1c[2][4][4];
    #pragma unroll
    for (int i = 0; i < 2; i++)
        #pragma unroll
        for (int j = 0; j < 4; j++)
            #pragma unroll
            for (int l = 0; l < 4; l++) { a0c[i][j][l] = 0.f; a1c[i][j][l] = 0.f; }

    const __half* t0 = g_t2 + (((size_t)(b*2 + 0) * C) << 12) + p0;
    const __half* t1 = g_t2 + (((size_t)(b*2 + 1) * C) << 12) + p0;
    const __half* W0 = g_wexp_h + (size_t)e0 * C * C;
    const __half* W1 = g_wexp_h + (size_t)e1 * C * C;

    int wco = tx >> 1, wk8 = tx & 1;
    int ex = tx >> 7, s7 = tx & 127;
    int k2 = s7 >> 4, bpx0 = (s7 & 15) << 2;
    const __half* tsel = ex ? t1 : t0;

    uint4 wraw0, wraw1; uint2 be, bo;
    wraw0 = *(const uint4*)&W0[wco * C + wk8 * 8];
    wraw1 = *(const uint4*)&W1[wco * C + wk8 * 8];
    be = *(const uint2*)&tsel[(size_t)(2 * k2) * P + bpx0];
    bo = *(const uint2*)&tsel[(size_t)(2 * k2 + 1) * P + bpx0];
    *(uint4*)&Wsm0[0][wco * WSE + wk8 * 4] = wraw0;
    *(uint4*)&Wsm1[0][wco * WSE + wk8 * 4] = wraw1;
    {
        unsigned* Bsel = ex ? Bsm1[0] : Bsm0[0];
        *(uint4*)&Bsel[k2 * BSP + bpx0] = zip_h4(be, bo);
    }
    __syncthreads();

    for (int ci = 0; ci < 8; ci++) {
        int cur = ci & 1;
        if (ci < 7) {
            int c0 = (ci + 1) * 16;
            wraw0 = *(const uint4*)&W0[wco * C + c0 + wk8 * 8];
            wraw1 = *(const uint4*)&W1[wco * C + c0 + wk8 * 8];
            be = *(const uint2*)&tsel[(size_t)(c0 + 2 * k2) * P + bpx0];
            bo = *(const uint2*)&tsel[(size_t)(c0 + 2 * k2 + 1) * P + bpx0];
        }
        const unsigned* Wc0 = Wsm0[cur];
        const unsigned* Wc1 = Wsm1[cur];
        const unsigned* Bc0 = Bsm0[cur];
        const unsigned* Bc1 = Bsm1[cur];
        unsigned af0[2][4], af1[2][4];
        #pragma unroll
        for (int mt = 0; mt < 2; mt++) {
            int r0 = wm * 32 + mt * 16 + g;
            af0[mt][0] = Wc0[r0 * WSE + t4];
            af0[mt][1] = Wc0[(r0 + 8) * WSE + t4];
            af0[mt][2] = Wc0[r0 * WSE + t4 + 4];
            af0[mt][3] = Wc0[(r0 + 8) * WSE + t4 + 4];
            af1[mt][0] = Wc1[r0 * WSE + t4];
            af1[mt][1] = Wc1[(r0 + 8) * WSE + t4];
            af1[mt][2] = Wc1[r0 * WSE + t4 + 4];
            af1[mt][3] = Wc1[(r0 + 8) * WSE + t4 + 4];
        }
        #pragma unroll
        for (int nt = 0; nt < 4; nt++) {
            int col = wn * 32 + nt * 8 + g;
            unsigned b00 = Bc0[t4 * BSP + col];
            unsigned b01 = Bc0[(t4 + 4) * BSP + col];
            unsigned b10 = Bc1[t4 * BSP + col];
            unsigned b11 = Bc1[(t4 + 4) * BSP + col];
            #pragma unroll
            for (int mt = 0; mt < 2; mt++) {
                mma_f16(a0c[mt][nt], af0[mt][0], af0[mt][1], af0[mt][2], af0[mt][3], b00, b01);
                mma_f16(a1c[mt][nt], af1[mt][0], af1[mt][1], af1[mt][2], af1[mt][3], b10, b11);
            }
        }
        if (ci < 7) {
            int nxt = 1 - cur;
            *(uint4*)&Wsm0[nxt][wco * WSE + wk8 * 4] = wraw0;
            *(uint4*)&Wsm1[nxt][wco * WSE + wk8 * 4] = wraw1;
            unsigned* Bsel = ex ? Bsm1[nxt] : Bsm0[nxt];
            *(uint4*)&Bsel[k2 * BSP + bpx0] = zip_h4(be, bo);
            __syncthreads();
        }
    }
    #pragma unroll
    for (int mt = 0; mt < 2; mt++) {
        int r0 = wm * 32 + mt * 16 + g;
        float b00 = bias[e0 * C + r0], b08 = bias[e0 * C + r0 + 8];
        float b10 = bias[e1 * C + r0], b18 = bias[e1 * C + r0 + 8];
        #pragma unroll
        for (int nt = 0; nt < 4; nt++) {
            int col = p0 + wn * 32 + nt * 8 + 2 * t4;
            float* o0 = out + ((((size_t)b * C) + r0) << 12) + col;
            float* o8 = out + ((((size_t)b * C) + r0 + 8) << 12) + col;
            float v0 = rw0 * silu_f(a0c[mt][nt][0] + b00) + rw1 * silu_f(a1c[mt][nt][0] + b10);
            float v1 = rw0 * silu_f(a0c[mt][nt][1] + b00) + rw1 * silu_f(a1c[mt][nt][1] + b10);
            float v2 = rw0 * silu_f(a0c[mt][nt][2] + b08) + rw1 * silu_f(a1c[mt][nt][2] + b18);
            float v3 = rw0 * silu_f(a0c[mt][nt][3] + b08) + rw1 * silu_f(a1c[mt][nt][3] + b18);
            *(float2*)o0 = make_float2(v0, v1);
            *(float2*)o8 = make_float2(v2, v3);
        }
    }
}

// ---------------- launch ----------------------------------------------------
extern "C" void kernel_launch(void* const* d_in, const int* in_sizes, int n_in,
                              void* d_out, int out_size) {
    const float* x         = (const float*)d_in[0];
    const float* t_emb     = (const float*)d_in[1];
    const float* c_emb     = (const float*)d_in[2];
    const float* proj_dw   = (const float*)d_in[3];
    const float* proj_dw_b = (const float*)d_in[4];
    const float* proj_pw   = (const float*)d_in[5];
    const float* proj_pw_b = (const float*)d_in[6];
    const float* r_w1      = (const float*)d_in[7];
    const float* r_b1      = (const float*)d_in[8];
    const float* r_w2      = (const float*)d_in[9];
    const float* r_b2      = (const float*)d_in[10];
    const float* exp_dw    = (const float*)d_in[11];
    const float* exp_dw_b  = (const float*)d_in[12];
    const float* exp_pw    = (const float*)d_in[13];
    const float* exp_pw_b  = (const float*)d_in[14];

    float* out        = (float*)d_out;
    float* out_logits = out + (size_t)Bn * C * P;

    dw_proj_kernel<<<(Bn*C*256 + 255) / 256, 256>>>(x, proj_dw, proj_dw_b, proj_pw, exp_pw);
    pw_proj_kernel<<<dim3(P / 64, Bn), 256>>>(proj_pw_b);
    router_kernel<<<Bn, 1024>>>(t_emb, c_emb, r_w1, r_b1, r_w2, r_b2, out_logits);
    dw_exp_kernel<<<(Bn*C*512 + 255) / 256, 256>>>(exp_dw, exp_dw_b);
    pw_exp_kernel<<<dim3(P / 64, Bn), 256>>>(exp_pw_b, out);
}

// round 16
// speedup vs baseline: 1.0542x; 1.0034x over previous
#include <cuda_runtime.h>
#include <cuda_fp16.h>
#include <math.h>

#define Bn 16
#define C  128
#define P  4096      // 64*64
#define TD 256
#define CD 256
#define E  8
#define NK 2

// ---------------- scratch (static device arrays) ---------------------------
__device__ __half g_t1[Bn*C*P];         // dwconv(proj) output (fp16)
__device__ __half g_xproj[Bn*C*P];      // x_proj (fp16)
__device__ __half g_t2[Bn*NK*C*P];      // expert dwconv outputs (fp16)
__device__ __half g_wproj_h[C*C];       // proj_pw weights, fp16 (pre-converted)
__device__ __half g_wexp_h[E*C*C];      // exp_pw weights, fp16 (pre-converted)
__device__ float  g_pooled[Bn*C];       // SUM over pixels (mean in router)
__device__ int    g_eidx[Bn*NK];
__device__ float  g_ew[Bn*NK];

__device__ __forceinline__ float silu_f(float v) {
    return v / (1.f + __expf(-v));
}

// D(16x8,f32) += A(16x16,f16) * B(16x8,f16)
__device__ __forceinline__ void mma_f16(float* c,
                                        unsigned a0, unsigned a1, unsigned a2, unsigned a3,
                                        unsigned b0, unsigned b1) {
    asm volatile("mma.sync.aligned.m16n8k16.row.col.f32.f16.f16.f32 "
                 "{%0,%1,%2,%3}, {%4,%5,%6,%7}, {%8,%9}, {%0,%1,%2,%3};"
                 : "+f"(c[0]), "+f"(c[1]), "+f"(c[2]), "+f"(c[3])
                 : "r"(a0), "r"(a1), "r"(a2), "r"(a3), "r"(b0), "r"(b1));
}

// pack 4 floats -> 4 halfs (8 bytes)
__device__ __forceinline__ uint2 pack_h4(float a, float b, float c, float d) {
    union { uint2 u; __half2 h[2]; } pk;
    pk.h[0] = __floats2half2_rn(a, b);
    pk.h[1] = __floats2half2_rn(c, d);
    return pk.u;
}
__device__ __forceinline__ float4 unpack_h4(uint2 u) {
    union { uint2 uu; __half2 h[2]; } pk; pk.uu = u;
    float2 f0 = __half22float2(pk.h[0]);
    float2 f1 = __half22float2(pk.h[1]);
    return make_float4(f0.x, f0.y, f1.x, f1.y);
}
// zip even/odd k rows (4 px each) into 4 half2 (k,k+1) words
__device__ __forceinline__ uint4 zip_h4(uint2 e, uint2 o) {
    uint4 r;
    r.x = __byte_perm(e.x, o.x, 0x5410);
    r.y = __byte_perm(e.x, o.x, 0x7632);
    r.z = __byte_perm(e.y, o.y, 0x5410);
    r.w = __byte_perm(e.y, o.y, 0x7632);
    return r;
}

// ---------------- 1) proj dw 3x3 (4px x 4 rows/thread) + zero + W cvt ------
__global__ void dw_proj_kernel(const float* __restrict__ x,
                               const float* __restrict__ w,
                               const float* __restrict__ bias,
                               const float* __restrict__ proj_pw,
                               const float* __restrict__ exp_pw) {
    int idx = blockIdx.x * blockDim.x + threadIdx.x;   // over Bn*C*256
    if (idx < Bn * C) g_pooled[idx] = 0.f;
    if (idx < C * C) g_wproj_h[idx] = __float2half_rn(proj_pw[idx]);
    if (idx < E * C * C) g_wexp_h[idx] = __float2half_rn(exp_pw[idx]);
    if (idx >= Bn*C*256) return;
    int q = idx & 255;
    int px0 = (q & 15) << 2;
    int py  = (q >> 4) << 2;          // 0,4,...,60
    int plane = idx >> 8;             // b*C + c
    int c = plane & 127;
    const float* xp = x + ((size_t)plane << 12);
    const float* wc = w + c * 9;
    float bb = bias[c];

    float4 m[6]; float rl[6], rr[6];
    #pragma unroll
    for (int r = 0; r < 6; r++) {
        int yy = py - 1 + r;
        if ((unsigned)yy < 64u) {
            const float* row = xp + (yy << 6);
            m[r] = *(const float4*)&row[px0];
            rl[r] = (px0 == 0)  ? 0.f : row[px0 - 1];
            rr[r] = (px0 == 60) ? 0.f : row[px0 + 4];
        } else {
            m[r] = make_float4(0.f, 0.f, 0.f, 0.f); rl[r] = 0.f; rr[r] = 0.f;
        }
    }
    float o[4][4];
    #pragma unroll
    for (int r = 0; r < 4; r++)
        #pragma unroll
        for (int i = 0; i < 4; i++) o[r][i] = bb;
    #pragma unroll
    for (int j = 0; j < 3; j++) {
        float w0 = wc[j*3], w1 = wc[j*3+1], w2 = wc[j*3+2];
        #pragma unroll
        for (int r = 0; r < 4; r++) {
            float4 a = m[r + j]; float al = rl[r + j], ar = rr[r + j];
            o[r][0] += w0*al  + w1*a.x + w2*a.y;
            o[r][1] += w0*a.x + w1*a.y + w2*a.z;
            o[r][2] += w0*a.y + w1*a.z + w2*a.w;
            o[r][3] += w0*a.z + w1*a.w + w2*ar;
        }
    }
    size_t base = ((size_t)plane << 12) + px0;
    #pragma unroll
    for (int r = 0; r < 4; r++)
        *(uint2*)&g_t1[base + ((py + r) << 6)] = pack_h4(o[r][0], o[r][1], o[r][2], o[r][3]);
}

// ---------------- 2) proj pw GEMM (fp16 MMA, double-buffered) + pool -------
#define WSP 20
#define BSP 72
__global__ __launch_bounds__(256)
void pw_proj_kernel(const float* __restrict__ bias) {
    int b  = blockIdx.y;
    int p0 = blockIdx.x * 64;
    int tx = threadIdx.x;
    int wid = tx >> 5, lane = tx & 31;
    int wm = wid >> 1, wn = wid & 1;
    int g = lane >> 2, t4 = lane & 3;
    __shared__ __align__(16) unsigned Wsm[2][128 * WSP];
    __shared__ __align__(16) unsigned Bsm[2][16 * BSP];
    float acc[2][4][4];
    #pragma unroll
    for (int i = 0; i < 2; i++)
        #pragma unroll
        for (int j = 0; j < 4; j++)
            #pragma unroll
            for (int l = 0; l < 4; l++) acc[i][j][l] = 0.f;

    const __half* tin = g_t1 + (((size_t)b * C) << 12) + p0;
    int wco[2], wk8[2];
    #pragma unroll
    for (int i = 0; i < 2; i++) { int s = i * 256 + tx; wco[i] = s >> 2; wk8[i] = s & 3; }
    int k2 = tx >> 4, bpx0 = (tx & 15) << 2;

    uint4 wraw[2]; uint2 be, bo;
    #pragma unroll
    for (int i = 0; i < 2; i++)
        wraw[i] = *(const uint4*)&g_wproj_h[wco[i] * C + wk8[i] * 8];
    be = *(const uint2*)&tin[(size_t)(2 * k2) * P + bpx0];
    bo = *(const uint2*)&tin[(size_t)(2 * k2 + 1) * P + bpx0];
    #pragma unroll
    for (int i = 0; i < 2; i++)
        *(uint4*)&Wsm[0][wco[i] * WSP + wk8[i] * 4] = wraw[i];
    *(uint4*)&Bsm[0][k2 * BSP + bpx0] = zip_h4(be, bo);
    __syncthreads();

    for (int ci = 0; ci < 4; ci++) {
        int cur = ci & 1;
        if (ci < 3) {                          // gmem loads for next chunk
            int c0 = (ci + 1) * 32;
            #pragma unroll
            for (int i = 0; i < 2; i++)
                wraw[i] = *(const uint4*)&g_wproj_h[wco[i] * C + c0 + wk8[i] * 8];
            be = *(const uint2*)&tin[(size_t)(c0 + 2 * k2) * P + bpx0];
            bo = *(const uint2*)&tin[(size_t)(c0 + 2 * k2 + 1) * P + bpx0];
        }
        const unsigned* Wc = Wsm[cur];
        const unsigned* Bc = Bsm[cur];
        #pragma unroll
        for (int kk = 0; kk < 2; kk++) {
            unsigned af[2][4];
            #pragma unroll
            for (int mt = 0; mt < 2; mt++) {
                int r0 = wm * 32 + mt * 16 + g;
                af[mt][0] = Wc[r0 * WSP + kk * 8 + t4];
                af[mt][1] = Wc[(r0 + 8) * WSP + kk * 8 + t4];
                af[mt][2] = Wc[r0 * WSP + kk * 8 + t4 + 4];
                af[mt][3] = Wc[(r0 + 8) * WSP + kk * 8 + t4 + 4];
            }
            #pragma unroll
            for (int nt = 0; nt < 4; nt++) {
                int col = wn * 32 + nt * 8 + g;
                unsigned b0 = Bc[(kk * 8 + t4) * BSP + col];
                unsigned b1 = Bc[(kk * 8 + t4 + 4) * BSP + col];
                #pragma unroll
                for (int mt = 0; mt < 2; mt++)
                    mma_f16(acc[mt][nt], af[mt][0], af[mt][1], af[mt][2], af[mt][3], b0, b1);
            }
        }
        if (ci < 3) {
            int nxt = 1 - cur;
            #pragma unroll
            for (int i = 0; i < 2; i++)
                *(uint4*)&Wsm[nxt][wco[i] * WSP + wk8[i] * 4] = wraw[i];
            *(uint4*)&Bsm[nxt][k2 * BSP + bpx0] = zip_h4(be, bo);
            __syncthreads();
        }
    }
    // epilogue: bias, store xproj (fp16), pooled partials (fp32)
    #pragma unroll
    for (int mt = 0; mt < 2; mt++) {
        int r0 = wm * 32 + mt * 16 + g;
        float bb0 = bias[r0], bb8 = bias[r0 + 8];
        float s0 = 0.f, s8 = 0.f;
        #pragma unroll
        for (int nt = 0; nt < 4; nt++) {
            int col = p0 + wn * 32 + nt * 8 + 2 * t4;
            __half* o0 = g_xproj + ((((size_t)b * C) + r0) << 12) + col;
            __half* o8 = g_xproj + ((((size_t)b * C) + r0 + 8) << 12) + col;
            float v0 = acc[mt][nt][0] + bb0, v1 = acc[mt][nt][1] + bb0;
            float v2 = acc[mt][nt][2] + bb8, v3 = acc[mt][nt][3] + bb8;
            *(__half2*)o0 = __floats2half2_rn(v0, v1);
            *(__half2*)o8 = __floats2half2_rn(v2, v3);
            s0 += v0 + v1; s8 += v2 + v3;
        }
        s0 += __shfl_down_sync(0xffffffffu, s0, 2, 4);
        s0 += __shfl_down_sync(0xffffffffu, s0, 1, 4);
        s8 += __shfl_down_sync(0xffffffffu, s8, 2, 4);
        s8 += __shfl_down_sync(0xffffffffu, s8, 1, 4);
        if (t4 == 0) {
            atomicAdd(&g_pooled[b * C + r0], s0);
            atomicAdd(&g_pooled[b * C + r0 + 8], s8);
        }
    }
}

// ---------------- 3) router: per-b block, fused MLP+top2 -------------------
__global__ __launch_bounds__(1024)
void router_kernel(const float* __restrict__ t_emb,
                   const float* __restrict__ c_emb,
                   const float* __restrict__ W1, const float* __restrict__ b1,
                   const float* __restrict__ W2, const float* __restrict__ b2,
                   float* __restrict__ out_logits) {
    int b = blockIdx.x;
    __shared__ float feat[C + TD + CD];
    __shared__ float hpart[8][C];
    __shared__ float h[C];
    __shared__ float lgp[8][E];
    __shared__ float lg[E];
    int t = threadIdx.x;
    if (t < C + TD + CD) {
        float v;
        if (t < C)            v = g_pooled[b * C + t] * (1.f / 4096.f);
        else if (t < C + TD)  v = t_emb[b * TD + (t - C)];
        else                  v = c_emb[b * CD + (t - C - TD)];
        feat[t] = v;
    }
    __syncthreads();
    int co = t & 127, chunk = t >> 7;
    {
        float a0 = 0.f, a1 = 0.f, a2 = 0.f, a3 = 0.f;
        int f0 = chunk * 80;
        #pragma unroll
        for (int f = f0; f < f0 + 80; f += 4) {
            a0 += feat[f]     * W1[f * C + co];
            a1 += feat[f + 1] * W1[(f + 1) * C + co];
            a2 += feat[f + 2] * W1[(f + 2) * C + co];
            a3 += feat[f + 3] * W1[(f + 3) * C + co];
        }
        hpart[chunk][co] = (a0 + a1) + (a2 + a3);
    }
    __syncthreads();
    if (t < C) {
        float v = b1[t];
        #pragma unroll
        for (int i = 0; i < 8; i++) v += hpart[i][t];
        h[t] = silu_f(v);
    }
    __syncthreads();
    if (t < 64) {
        int e = t & 7, pp = t >> 3;
        float a = 0.f;
        int c0 = pp * 16;
        #pragma unroll
        for (int ci = c0; ci < c0 + 16; ci++) a += h[ci] * W2[ci * E + e];
        lgp[pp][e] = a;
    }
    __syncthreads();
    if (t < E) {
        float a = b2[t];
        #pragma unroll
        for (int i = 0; i < 8; i++) a += lgp[i][t];
        lg[t] = a;
        out_logits[b * E + t] = a;
    }
    __syncthreads();
    if (t == 0) {
        int i0 = 0; float v0 = lg[0];
        for (int e = 1; e < E; e++) if (lg[e] > v0) { v0 = lg[e]; i0 = e; }
        int i1 = -1; float v1 = -3.0e38f;
        for (int e = 0; e < E; e++) {
            if (e == i0) continue;
            if (lg[e] > v1) { v1 = lg[e]; i1 = e; }
        }
        float w0 = 1.f / (1.f + __expf(v1 - v0));
        g_eidx[b*2]   = i0;  g_eidx[b*2+1] = i1;
        g_ew[b*2]     = w0;  g_ew[b*2+1]   = 1.f - w0;
    }
}

// ---------------- 4) expert dw 3x3 — 2 experts, 4px x 4 rows / thread ------
__global__ void dw_exp_kernel(const float* __restrict__ w,
                              const float* __restrict__ bias) {
    int idx = blockIdx.x * blockDim.x + threadIdx.x;   // over Bn*C*256
    if (idx >= Bn*C*256) return;
    int q = idx & 255;
    int px0 = (q & 15) << 2;
    int py  = (q >> 4) << 2;          // 0,4,...,60
    int plane = idx >> 8;             // b*C + c
    int c = plane & 127;
    int b = plane >> 7;
    int e0 = g_eidx[b*2], e1 = g_eidx[b*2+1];
    const __half* xp = g_xproj + ((size_t)plane << 12);
    const float* wcA = w + ((size_t)e0 * C + c) * 9;
    const float* wcB = w + ((size_t)e1 * C + c) * 9;

    float4 m[6]; float rl[6], rr[6];
    #pragma unroll
    for (int r = 0; r < 6; r++) {
        int yy = py - 1 + r;
        if ((unsigned)yy < 64u) {
            const __half* row = xp + (yy << 6);
            m[r] = unpack_h4(*(const uint2*)&row[px0]);
            rl[r] = (px0 == 0)  ? 0.f : __half2float(row[px0 - 1]);
            rr[r] = (px0 == 60) ? 0.f : __half2float(row[px0 + 4]);
        } else {
            m[r] = make_float4(0.f, 0.f, 0.f, 0.f); rl[r] = 0.f; rr[r] = 0.f;
        }
    }
    size_t baseA = ((size_t)((b*2 + 0) * C + c) << 12) + px0;
    size_t baseB = ((size_t)((b*2 + 1) * C + c) << 12) + px0;
    // expert A pass (keeps peak live accumulators at 16)
    {
        float bA = bias[e0 * C + c];
        float o[4][4];
        #pragma unroll
        for (int r = 0; r < 4; r++)
            #pragma unroll
            for (int i = 0; i < 4; i++) o[r][i] = bA;
        #pragma unroll
        for (int j = 0; j < 3; j++) {
            float w0 = wcA[j*3], w1 = wcA[j*3+1], w2 = wcA[j*3+2];
            #pragma unroll
            for (int r = 0; r < 4; r++) {
                float4 a = m[r + j]; float al = rl[r + j], ar = rr[r + j];
                o[r][0] += w0*al  + w1*a.x + w2*a.y;
                o[r][1] += w0*a.x + w1*a.y + w2*a.z;
                o[r][2] += w0*a.y + w1*a.z + w2*a.w;
                o[r][3] += w0*a.z + w1*a.w + w2*ar;
            }
        }
        #pragma unroll
        for (int r = 0; r < 4; r++)
            *(uint2*)&g_t2[baseA + ((py + r) << 6)] =
                pack_h4(o[r][0], o[r][1], o[r][2], o[r][3]);
    }
    // expert B pass (window m/rl/rr reused)
    {
        float bB = bias[e1 * C + c];
        float o[4][4];
        #pragma unroll
        for (int r = 0; r < 4; r++)
            #pragma unroll
            for (int i = 0; i < 4; i++) o[r][i] = bB;
        #pragma unroll
        for (int j = 0; j < 3; j++) {
            float w0 = wcB[j*3], w1 = wcB[j*3+1], w2 = wcB[j*3+2];
            #pragma unroll
            for (int r = 0; r < 4; r++) {
                float4 a = m[r + j]; float al = rl[r + j], ar = rr[r + j];
                o[r][0] += w0*al  + w1*a.x + w2*a.y;
                o[r][1] += w0*a.x + w1*a.y + w2*a.z;
                o[r][2] += w0*a.y + w1*a.z + w2*a.w;
                o[r][3] += w0*a.z + w1*a.w + w2*ar;
            }
        }
        #pragma unroll
        for (int r = 0; r < 4; r++)
            *(uint2*)&g_t2[baseB + ((py + r) << 6)] =
                pack_h4(o[r][0], o[r][1], o[r][2], o[r][3]);
    }
}

// ---------------- 5) expert pw GEMM x2 (fp16 MMA, double-buffered) ---------
#define WSE 12
__global__ __launch_bounds__(256, 2)
void pw_exp_kernel(const float* __restrict__ bias, float* __restrict__ out) {
    int b  = blockIdx.y;
    int p0 = blockIdx.x * 64;
    int tx = threadIdx.x;
    int wid = tx >> 5, lane = tx & 31;
    int wm = wid >> 1, wn = wid & 1;
    int g = lane >> 2, t4 = lane & 3;
    int e0 = g_eidx[b*2], e1 = g_eidx[b*2+1];
    float rw0 = g_ew[b*2], rw1 = g_ew[b*2+1];
    __shared__ __align__(16) unsigned Wsm0[2][128 * WSE], Wsm1[2][128 * WSE];
    __shared__ __align__(16) unsigned Bsm0[2][8 * BSP],   Bsm1[2][8 * BSP];
    float a0c[2][4][4], a1c[2][4][4];
    #pragma unroll
    for (int i = 0; i < 2; i++)
        #pragma unroll
        for (int j = 0; j < 4; j++)
            #pragma unroll
            for (int l = 0; l < 4; l++) { a0c[i][j][l] = 0.f; a1c[i][j][l] = 0.f; }

    const __half* t0 = g_t2 + (((size_t)(b*2 + 0) * C) << 12) + p0;
    const __half* t1 = g_t2 + (((size_t)(b*2 + 1) * C) << 12) + p0;
    const __half* W0 = g_wexp_h + (size_t)e0 * C * C;
    const __half* W1 = g_wexp_h + (size_t)e1 * C * C;

    int wco = tx >> 1, wk8 = tx & 1;
    int ex = tx >> 7, s7 = tx & 127;
    int k2 = s7 >> 4, bpx0 = (s7 & 15) << 2;
    const __half* tsel = ex ? t1 : t0;

    uint4 wraw0, wraw1; uint2 be, bo;
    wraw0 = *(const uint4*)&W0[wco * C + wk8 * 8];
    wraw1 = *(const uint4*)&W1[wco * C + wk8 * 8];
    be = *(const uint2*)&tsel[(size_t)(2 * k2) * P + bpx0];
    bo = *(const uint2*)&tsel[(size_t)(2 * k2 + 1) * P + bpx0];
    *(uint4*)&Wsm0[0][wco * WSE + wk8 * 4] = wraw0;
    *(uint4*)&Wsm1[0][wco * WSE + wk8 * 4] = wraw1;
    {
        unsigned* Bsel = ex ? Bsm1[0] : Bsm0[0];
        *(uint4*)&Bsel[k2 * BSP + bpx0] = zip_h4(be, bo);
    }
    __syncthreads();

    for (int ci = 0; ci < 8; ci++) {
        int cur = ci & 1;
        if (ci < 7) {
            int c0 = (ci + 1) * 16;
            wraw0 = *(const uint4*)&W0[wco * C + c0 + wk8 * 8];
            wraw1 = *(const uint4*)&W1[wco * C + c0 + wk8 * 8];
            be = *(const uint2*)&tsel[(size_t)(c0 + 2 * k2) * P + bpx0];
            bo = *(const uint2*)&tsel[(size_t)(c0 + 2 * k2 + 1) * P + bpx0];
        }
        const unsigned* Wc0 = Wsm0[cur];
        const unsigned* Wc1 = Wsm1[cur];
        const unsigned* Bc0 = Bsm0[cur];
        const unsigned* Bc1 = Bsm1[cur];
        unsigned af0[2][4], af1[2][4];
        #pragma unroll
        for (int mt = 0; mt < 2; mt++) {
            int r0 = wm * 32 + mt * 16 + g;
            af0[mt][0] = Wc0[r0 * WSE + t4];
            af0[mt][1] = Wc0[(r0 + 8) * WSE + t4];
            af0[mt][2] = Wc0[r0 * WSE + t4 + 4];
            af0[mt][3] = Wc0[(r0 + 8) * WSE + t4 + 4];
            af1[mt][0] = Wc1[r0 * WSE + t4];
            af1[mt][1] = Wc1[(r0 + 8) * WSE + t4];
            af1[mt][2] = Wc1[r0 * WSE + t4 + 4];
            af1[mt][3] = Wc1[(r0 + 8) * WSE + t4 + 4];
        }
        #pragma unroll
        for (int nt = 0; nt < 4; nt++) {
            int col = wn * 32 + nt * 8 + g;
            unsigned b00 = Bc0[t4 * BSP + col];
            unsigned b01 = Bc0[(t4 + 4) * BSP + col];
            unsigned b10 = Bc1[t4 * BSP + col];
            unsigned b11 = Bc1[(t4 + 4) * BSP + col];
            #pragma unroll
            for (int mt = 0; mt < 2; mt++) {
                mma_f16(a0c[mt][nt], af0[mt][0], af0[mt][1], af0[mt][2], af0[mt][3], b00, b01);
                mma_f16(a1c[mt][nt], af1[mt][0], af1[mt][1], af1[mt][2], af1[mt][3], b10, b11);
            }
        }
        if (ci < 7) {
            int nxt = 1 - cur;
            *(uint4*)&Wsm0[nxt][wco * WSE + wk8 * 4] = wraw0;
            *(uint4*)&Wsm1[nxt][wco * WSE + wk8 * 4] = wraw1;
            unsigned* Bsel = ex ? Bsm1[nxt] : Bsm0[nxt];
            *(uint4*)&Bsel[k2 * BSP + bpx0] = zip_h4(be, bo);
            __syncthreads();
        }
    }
    #pragma unroll
    for (int mt = 0; mt < 2; mt++) {
        int r0 = wm * 32 + mt * 16 + g;
        float b00 = bias[e0 * C + r0], b08 = bias[e0 * C + r0 + 8];
        float b10 = bias[e1 * C + r0], b18 = bias[e1 * C + r0 + 8];
        #pragma unroll
        for (int nt = 0; nt < 4; nt++) {
            int col = p0 + wn * 32 + nt * 8 + 2 * t4;
            float* o0 = out + ((((size_t)b * C) + r0) << 12) + col;
            float* o8 = out + ((((size_t)b * C) + r0 + 8) << 12) + col;
            float v0 = rw0 * silu_f(a0c[mt][nt][0] + b00) + rw1 * silu_f(a1c[mt][nt][0] + b10);
            float v1 = rw0 * silu_f(a0c[mt][nt][1] + b00) + rw1 * silu_f(a1c[mt][nt][1] + b10);
            float v2 = rw0 * silu_f(a0c[mt][nt][2] + b08) + rw1 * silu_f(a1c[mt][nt][2] + b18);
            float v3 = rw0 * silu_f(a0c[mt][nt][3] + b08) + rw1 * silu_f(a1c[mt][nt][3] + b18);
            *(float2*)o0 = make_float2(v0, v1);
            *(float2*)o8 = make_float2(v2, v3);
        }
    }
}

// ---------------- launch ----------------------------------------------------
extern "C" void kernel_launch(void* const* d_in, const int* in_sizes, int n_in,
                              void* d_out, int out_size) {
    const float* x         = (const float*)d_in[0];
    const float* t_emb     = (const float*)d_in[1];
    const float* c_emb     = (const float*)d_in[2];
    const float* proj_dw   = (const float*)d_in[3];
    const float* proj_dw_b = (const float*)d_in[4];
    const float* proj_pw   = (const float*)d_in[5];
    const float* proj_pw_b = (const float*)d_in[6];
    const float* r_w1      = (const float*)d_in[7];
    const float* r_b1      = (const float*)d_in[8];
    const float* r_w2      = (const float*)d_in[9];
    const float* r_b2      = (const float*)d_in[10];
    const float* exp_dw    = (const float*)d_in[11];
    const float* exp_dw_b  = (const float*)d_in[12];
    const float* exp_pw    = (const float*)d_in[13];
    const float* exp_pw_b  = (const float*)d_in[14];

    float* out        = (float*)d_out;
    float* out_logits = out + (size_t)Bn * C * P;

    dw_proj_kernel<<<(Bn*C*256 + 255) / 256, 256>>>(x, proj_dw, proj_dw_b, proj_pw, exp_pw);
    pw_proj_kernel<<<dim3(P / 64, Bn), 256>>>(proj_pw_b);
    router_kernel<<<Bn, 1024>>>(t_emb, c_emb, r_w1, r_b1, r_w2, r_b2, out_logits);
    dw_exp_kernel<<<(Bn*C*256 + 255) / 256, 256>>>(exp_dw, exp_dw_b);
    pw_exp_kernel<<<dim3(P / 64, Bn), 256>>>(exp_pw_b, out);
}